// round 6
// baseline (speedup 1.0000x reference)
#include <cuda_runtime.h>
#include <cuda_bf16.h>
#include <math.h>
#include <stdint.h>

// Problem constants
#define T_STEPS 128
#define BATCH   256
#define V_DIM   256
#define N_DIM   1024
#define TB      (T_STEPS * BATCH)          // 32768
#define SLAB    (BATCH * N_DIM)            // 262144 floats per time slab

// Scratch (device globals: no allocations allowed)
__device__ float g_seq[(size_t)T_STEPS * SLAB];   // 128 MB: xw pre-activations, then h_t in place
__device__ float g_logits[(size_t)TB * V_DIM];    // 33.5 MB
__device__ float g_rowloss[TB];

__device__ __forceinline__ uint32_t f2tf32(float x) {
    uint32_t r;
    asm("cvt.rna.tf32.f32 %0, %1;" : "=r"(r) : "f"(x));
    return r;
}

__device__ __forceinline__ void mma_tf32(float c[4], uint32_t a0, uint32_t a1,
                                         uint32_t a2, uint32_t a3,
                                         uint32_t b0, uint32_t b1) {
    asm volatile(
        "mma.sync.aligned.m16n8k8.row.col.f32.tf32.tf32.f32 "
        "{%0,%1,%2,%3}, {%4,%5,%6,%7}, {%8,%9}, {%0,%1,%2,%3};"
        : "+f"(c[0]), "+f"(c[1]), "+f"(c[2]), "+f"(c[3])
        : "r"(a0), "r"(a1), "r"(a2), "r"(a3), "r"(b0), "r"(b1));
}

// ---------------------------------------------------------------------------
// tf32 tensor-core GEMM: C[M,N] = A[M,K] @ B[K,N]  (row-major fp32 in gmem)
// Block tile 64x64, 128 threads = 4 warps (2x2), each warp 32x32.
// C = acc + bias[col].
// ---------------------------------------------------------------------------
#define AS_STRIDE 20   // words; conflict-free A-fragment LDS (BK=16)
#define BS_STRIDE 72   // words; conflict-free B-fragment LDS

__global__ void __launch_bounds__(128)
mma_gemm(const float* __restrict__ A, const float* __restrict__ B,
         float* __restrict__ C, const float* __restrict__ bias,
         int lda, int ldb, int ldc, int K)
{
    __shared__ uint32_t As[64 * AS_STRIDE];   // [m][k] tf32 bits, 64x16 tile
    __shared__ uint32_t Bs[16 * BS_STRIDE];   // [k][n] tf32 bits, 16x64 tile

    const int tid  = threadIdx.x;
    const int warp = tid >> 5;
    const int lane = tid & 31;
    const int gid  = lane >> 2;
    const int tg   = lane & 3;

    const int wm = (warp >> 1) * 32;
    const int wn = (warp & 1) * 32;

    const int row0 = blockIdx.y * 64;
    const int col0 = blockIdx.x * 64;

    const int a_r0 = tid >> 2;
    const int a_c4 = (tid & 3) * 4;
    const int b_r0 = tid >> 4;
    const int b_c4 = (tid & 15) * 4;

    float acc[2][4][4] = {};

    for (int kt = 0; kt < K; kt += 16) {
#pragma unroll
        for (int h = 0; h < 2; h++) {
            int ar = a_r0 + h * 32;
            float4 av = *(const float4*)(A + (size_t)(row0 + ar) * lda + (kt + a_c4));
            uint32_t* dst = &As[ar * AS_STRIDE + a_c4];
            dst[0] = f2tf32(av.x); dst[1] = f2tf32(av.y);
            dst[2] = f2tf32(av.z); dst[3] = f2tf32(av.w);
        }
#pragma unroll
        for (int h = 0; h < 2; h++) {
            int br = b_r0 + h * 8;
            float4 bv = *(const float4*)(B + (size_t)(kt + br) * ldb + (col0 + b_c4));
            uint32_t* dst = &Bs[br * BS_STRIDE + b_c4];
            dst[0] = f2tf32(bv.x); dst[1] = f2tf32(bv.y);
            dst[2] = f2tf32(bv.z); dst[3] = f2tf32(bv.w);
        }
        __syncthreads();

#pragma unroll
        for (int ks = 0; ks < 2; ks++) {
            const int kk = ks * 8;
            uint32_t afrag[2][4];
#pragma unroll
            for (int mi = 0; mi < 2; mi++) {
                int r = wm + mi * 16 + gid;
                afrag[mi][0] = As[(r    ) * AS_STRIDE + kk + tg    ];
                afrag[mi][1] = As[(r + 8) * AS_STRIDE + kk + tg    ];
                afrag[mi][2] = As[(r    ) * AS_STRIDE + kk + tg + 4];
                afrag[mi][3] = As[(r + 8) * AS_STRIDE + kk + tg + 4];
            }
#pragma unroll
            for (int ni = 0; ni < 4; ni++) {
                int c = wn + ni * 8 + gid;
                uint32_t b0 = Bs[(kk + tg    ) * BS_STRIDE + c];
                uint32_t b1 = Bs[(kk + tg + 4) * BS_STRIDE + c];
#pragma unroll
                for (int mi = 0; mi < 2; mi++)
                    mma_tf32(acc[mi][ni], afrag[mi][0], afrag[mi][1],
                             afrag[mi][2], afrag[mi][3], b0, b1);
            }
        }
        __syncthreads();
    }

#pragma unroll
    for (int mi = 0; mi < 2; mi++) {
        int r0 = row0 + wm + mi * 16 + gid;
#pragma unroll
        for (int ni = 0; ni < 4; ni++) {
            int c = col0 + wn + ni * 8 + tg * 2;
            float b0 = bias[c], b1 = bias[c + 1];
            float2 v0 = make_float2(acc[mi][ni][0] + b0, acc[mi][ni][1] + b1);
            float2 v1 = make_float2(acc[mi][ni][2] + b0, acc[mi][ni][3] + b1);
            *(float2*)(C + (size_t)r0 * ldc + c)       = v0;
            *(float2*)(C + (size_t)(r0 + 8) * ldc + c) = v1;
        }
    }
}

// ---------------------------------------------------------------------------
// Persistent recurrence kernel.
// 128 blocks (1/SM, co-resident), block = 256 threads = 8 warps (4m x 2n),
// block tile 64(m) x 32(n), warp tile 16x16. Wh column slice lives in SMEM
// for the whole kernel. Grid-wide software barrier between steps.
// ---------------------------------------------------------------------------
#define RNN_BLOCKS 128
#define WS_STRIDE  40   // k-row stride (words): 40 % 32 == 8 -> conflict-free B frags
#define PAS_STRIDE 36   // m-row stride (words): 36 % 32 == 4 -> conflict-free A frags
#define RNN_SMEM_WORDS (1024 * WS_STRIDE + 2 * 64 * PAS_STRIDE)
#define RNN_SMEM_BYTES (RNN_SMEM_WORDS * 4)

__device__ unsigned g_bar_cnt;               // zero-init; returns to 0 after each barrier
__device__ volatile unsigned g_bar_gen;      // monotonically increasing generation

__device__ __forceinline__ void grid_sync()
{
    __syncthreads();
    if (threadIdx.x == 0) {
        unsigned gen = g_bar_gen;
        __threadfence();
        unsigned old = atomicInc(&g_bar_cnt, RNN_BLOCKS - 1);
        if (old == RNN_BLOCKS - 1) {
            __threadfence();
            g_bar_gen = gen + 1;
        } else {
            while (g_bar_gen == gen) { __nanosleep(32); }
        }
        __threadfence();
    }
    __syncthreads();
}

__global__ void __launch_bounds__(256, 1)
rnn_persistent(float* __restrict__ seq, const float* __restrict__ wh)
{
    extern __shared__ uint32_t sm[];
    uint32_t* Ws = sm;                         // [1024][WS_STRIDE]
    uint32_t* As = sm + 1024 * WS_STRIDE;      // [2][64][PAS_STRIDE]

    const int tid  = threadIdx.x;
    const int warp = tid >> 5;
    const int lane = tid & 31;
    const int gid  = lane >> 2;
    const int tg   = lane & 3;
    const int wm   = (warp >> 1) * 16;         // 0,16,32,48
    const int wn   = (warp & 1) * 16;          // 0,16

    const int n0 = (blockIdx.x & 31) * 32;
    const int m0 = (blockIdx.x >> 5) * 64;

    // ---- one-time: stage Wh[:, n0:n0+32] as tf32 in SMEM ----
    for (int idx = tid; idx < 1024 * 8; idx += 256) {
        int r  = idx >> 3;
        int c4 = (idx & 7) * 4;
        float4 v = *(const float4*)(wh + (size_t)r * N_DIM + n0 + c4);
        uint32_t* d = &Ws[r * WS_STRIDE + c4];
        d[0] = f2tf32(v.x); d[1] = f2tf32(v.y);
        d[2] = f2tf32(v.z); d[3] = f2tf32(v.w);
    }

    // ---- h0 = tanh(pre0) on this block's tile ----
    for (int idx = tid; idx < 64 * 8; idx += 256) {
        int r  = idx >> 3;
        int c4 = (idx & 7) * 4;
        float4* p = (float4*)(seq + (size_t)(m0 + r) * N_DIM + n0 + c4);
        float4 v = *p;
        v.x = tanhf(v.x); v.y = tanhf(v.y); v.z = tanhf(v.z); v.w = tanhf(v.w);
        *p = v;
    }
    __threadfence();
    grid_sync();

    // A loader mapping: thread -> rows (tid>>3), (tid>>3)+32; 4 cols at (tid&7)*4
    const int a_r  = tid >> 3;
    const int a_c4 = (tid & 7) * 4;

    for (int t = 1; t < T_STEPS; t++) {
        const float* hp  = seq + (size_t)(t - 1) * SLAB;
        float*       cur = seq + (size_t)t * SLAB;

        float acc[2][4] = {};

        // prefetch kt = 0
        float4 ra = *(const float4*)(hp + (size_t)(m0 + a_r)      * N_DIM + a_c4);
        float4 rb = *(const float4*)(hp + (size_t)(m0 + a_r + 32) * N_DIM + a_c4);

        for (int kt = 0; kt < N_DIM; kt += 32) {
            uint32_t* buf = As + ((kt >> 5) & 1) * (64 * PAS_STRIDE);

            uint4 pa, pb;
            pa.x = f2tf32(ra.x); pa.y = f2tf32(ra.y); pa.z = f2tf32(ra.z); pa.w = f2tf32(ra.w);
            pb.x = f2tf32(rb.x); pb.y = f2tf32(rb.y); pb.z = f2tf32(rb.z); pb.w = f2tf32(rb.w);
            *(uint4*)&buf[(a_r     ) * PAS_STRIDE + a_c4] = pa;
            *(uint4*)&buf[(a_r + 32) * PAS_STRIDE + a_c4] = pb;
            __syncthreads();

            // prefetch next A tile during mma (hides LDG latency)
            float4 na = ra, nb = rb;
            if (kt + 32 < N_DIM) {
                na = *(const float4*)(hp + (size_t)(m0 + a_r)      * N_DIM + kt + 32 + a_c4);
                nb = *(const float4*)(hp + (size_t)(m0 + a_r + 32) * N_DIM + kt + 32 + a_c4);
            }

#pragma unroll
            for (int ks = 0; ks < 4; ks++) {
                const int kk = ks * 8;
                int r = wm + gid;
                uint32_t a0 = buf[(r    ) * PAS_STRIDE + kk + tg    ];
                uint32_t a1 = buf[(r + 8) * PAS_STRIDE + kk + tg    ];
                uint32_t a2 = buf[(r    ) * PAS_STRIDE + kk + tg + 4];
                uint32_t a3 = buf[(r + 8) * PAS_STRIDE + kk + tg + 4];
#pragma unroll
                for (int ni = 0; ni < 2; ni++) {
                    int c = wn + ni * 8 + gid;
                    uint32_t b0 = Ws[(kt + kk + tg    ) * WS_STRIDE + c];
                    uint32_t b1 = Ws[(kt + kk + tg + 4) * WS_STRIDE + c];
                    mma_tf32(acc[ni], a0, a1, a2, a3, b0, b1);
                }
            }
            ra = na; rb = nb;
        }

        // epilogue: h = tanh(pre + acc), in place
#pragma unroll
        for (int ni = 0; ni < 2; ni++) {
            int c  = n0 + wn + ni * 8 + tg * 2;
            int r0 = m0 + wm + gid;
            float2 p0 = *(float2*)(cur + (size_t)r0 * N_DIM + c);
            float2 p1 = *(float2*)(cur + (size_t)(r0 + 8) * N_DIM + c);
            float2 o0 = make_float2(tanhf(acc[ni][0] + p0.x), tanhf(acc[ni][1] + p0.y));
            float2 o1 = make_float2(tanhf(acc[ni][2] + p1.x), tanhf(acc[ni][3] + p1.y));
            *(float2*)(cur + (size_t)r0 * N_DIM + c)       = o0;
            *(float2*)(cur + (size_t)(r0 + 8) * N_DIM + c) = o1;
        }
        __threadfence();
        grid_sync();
    }
}

// Per-row soft-label cross-entropy from raw logits.
__global__ void loss_rows(const float* __restrict__ logits,
                          const float* __restrict__ labels,
                          float* __restrict__ rowloss)
{
    const int row = blockIdx.x;
    const int v = threadIdx.x;
    __shared__ float s[256];

    size_t base = (size_t)row * V_DIM;
    float logit = logits[base + v];
    float lab   = labels[base + v];

    s[v] = logit; __syncthreads();
    for (int o = 128; o > 0; o >>= 1) {
        if (v < o) s[v] = fmaxf(s[v], s[v + o]);
        __syncthreads();
    }
    float mx = s[0]; __syncthreads();

    s[v] = expf(logit - mx); __syncthreads();
    for (int o = 128; o > 0; o >>= 1) {
        if (v < o) s[v] += s[v + o];
        __syncthreads();
    }
    float Z = s[0]; __syncthreads();

    s[v] = lab; __syncthreads();
    for (int o = 128; o > 0; o >>= 1) {
        if (v < o) s[v] += s[v + o];
        __syncthreads();
    }
    float sumLab = s[0]; __syncthreads();

    s[v] = lab * logit; __syncthreads();
    for (int o = 128; o > 0; o >>= 1) {
        if (v < o) s[v] += s[v + o];
        __syncthreads();
    }
    float sumLL = s[0];

    if (v == 0)
        rowloss[row] = (mx + logf(Z)) * sumLab - sumLL;
}

// Deterministic final mean over 32768 row losses.
__global__ void final_reduce(const float* __restrict__ rowloss, float* __restrict__ out)
{
    const int v = threadIdx.x;   // 256 threads
    __shared__ float s[256];
    float acc = 0.0f;
    for (int i = v; i < TB; i += 256) acc += rowloss[i];
    s[v] = acc; __syncthreads();
    for (int o = 128; o > 0; o >>= 1) {
        if (v < o) s[v] += s[v + o];
        __syncthreads();
    }
    if (v == 0) out[0] = s[0] * (1.0f / (float)TB);
}

extern "C" void kernel_launch(void* const* d_in, const int* in_sizes, int n_in,
                              void* d_out, int out_size)
{
    const float* inputs  = (const float*)d_in[0];   // (T, B, V)
    const float* labels  = (const float*)d_in[1];   // (T*B, V)
    const float* weights = (const float*)d_in[2];   // (V+N, N)
    const float* bias    = (const float*)d_in[3];   // (N,)
    const float* ow      = (const float*)d_in[4];   // (N, V)
    const float* ob      = (const float*)d_in[5];   // (V,)
    float* out = (float*)d_out;

    float *seq, *logits, *rowloss;
    cudaGetSymbolAddress((void**)&seq, g_seq);
    cudaGetSymbolAddress((void**)&logits, g_logits);
    cudaGetSymbolAddress((void**)&rowloss, g_rowloss);

    const float* wx = weights;                         // rows [0, V)
    const float* wh = weights + (size_t)V_DIM * N_DIM; // rows [V, V+N)

    cudaFuncSetAttribute(rnn_persistent,
                         cudaFuncAttributeMaxDynamicSharedMemorySize, RNN_SMEM_BYTES);

    // 1) pre[t,b,n] = X @ Wx + bias  (full sequence, one big GEMM)
    mma_gemm<<<dim3(N_DIM / 64, TB / 64, 1), 128>>>(
        inputs, wx, seq, bias, V_DIM, N_DIM, N_DIM, V_DIM);

    // 2+3) full recurrence in one persistent kernel (h0 tanh fused inside)
    rnn_persistent<<<RNN_BLOCKS, 256, RNN_SMEM_BYTES>>>(seq, wh);

    // 4) logits = H @ Wo + ob
    mma_gemm<<<dim3(V_DIM / 64, TB / 64, 1), 128>>>(
        seq, ow, logits, ob, N_DIM, V_DIM, V_DIM, N_DIM);

    // 5) per-row loss, then deterministic mean
    loss_rows<<<TB, 256>>>(logits, labels, rowloss);
    final_reduce<<<1, 256>>>(rowloss, out);
}